// round 10
// baseline (speedup 1.0000x reference)
#include <cuda_runtime.h>
#include <math.h>

#define MAXD 2048
#define TILE 32
#define NTMAX (MAXD / TILE)     // 64
#define ETA 0.005f

// Disjoint partials: slot [p][j] = contribution of tile p to column/row j.
// Every slot written exactly once per launch -> no zeroing, no atomics, no fences.
__device__ float g_partM[NTMAX][MAXD];   // 512 KB
__device__ float g_partR[NTMAX][MAXD];   // 512 KB
__device__ float g_m[MAXD];              // m[j]           (pre-scaled by 1/D)
__device__ float g_rm[MAXD];             // rowmean[b] * ETA / D

// ---------------------------------------------------------------------------
// Kernel 1: symmetric tile-pair reduction, issue-optimized.
// Tiles stored as float4[32][8] with XOR swizzle slot = c4 ^ (r&7):
//   - fill:       1 LDG.128 + 1 STS.128 per thread (conflict-free)
//   - row reads:  LDS.128, slot g^(l&7)   (conflict-free per quarter-warp)
//   - col reads:  scalar, 8 slots x 4 words = 32 banks (conflict-free)
// Both passes computed back-to-back (read-only on A/B), ONE reduction sync,
// warps 0/1 reduce pass1/pass2 partials in parallel.
// Block {I,J}, I<=J: A = x[I,J], B = x[J,I].
//   pass 1: partM[I][J*32+l] = sum_u A[u][l]*B[l][u]; partR[I][J*32+l] = sum_u B[l][u]
//   pass 2: partM[J][I*32+l] = sum_v A[l][v]*B[v][l]; partR[J][I*32+l] = sum_v A[l][v]
// Diagonal (I==J): pass 1 only with B := A.
// ---------------------------------------------------------------------------
__global__ void __launch_bounds__(256) hebb_tile_kernel(
    const float* __restrict__ x, int D, int NT)
{
    __shared__ float4 A4[32][8];
    __shared__ float4 B4[32][8];
    __shared__ float2 redA[8][32];
    __shared__ float2 redB[8][32];

    // Invert triangular index: bid -> (I, J), I <= J, row-major upper.
    const int t = blockIdx.x;
    const float fN = 2.0f * (float)NT + 1.0f;
    int I = (int)((fN - sqrtf(fN * fN - 8.0f * (float)t)) * 0.5f);
    #define TRI_BASE(i) ((i) * NT - ((i) * ((i) - 1)) / 2)
    while (I > 0 && TRI_BASE(I) > t) I--;
    while (TRI_BASE(I + 1) <= t) I++;
    const int J = I + (t - TRI_BASE(I));
    #undef TRI_BASE

    const int tid = threadIdx.x;
    const int r   = tid >> 3;          // 0..31 (row within tile)
    const int c4  = tid & 7;           // float4 column
    const bool diag = (I == J);

    // Fill tiles: one LDG.128 -> one swizzled STS.128.
    A4[r][c4 ^ (r & 7)] = *reinterpret_cast<const float4*>(
        x + (size_t)(I * TILE + r) * D + J * TILE + (c4 << 2));
    if (!diag)
        B4[r][c4 ^ (r & 7)] = *reinterpret_cast<const float4*>(
            x + (size_t)(J * TILE + r) * D + I * TILE + (c4 << 2));
    __syncthreads();

    const float* Af = reinterpret_cast<const float*>(A4);
    const float* Bf = diag ? Af : reinterpret_cast<const float*>(B4);
    const float4 (*Bq)[8] = diag ? A4 : B4;

    const int g  = tid >> 5;           // 0..7  (warp id / 4-element group)
    const int l  = tid & 31;           // lane  (col in pass1 / row in pass2)
    const int u0 = g << 2;

    // Shared scalar indices: element (u0+k, l) of a swizzled tile.
    const int lw = l & 3;
    const int ls = l >> 2;
    const int i0 = (u0 + 0) * 32 + (((ls ^ ((u0 + 0) & 7)) << 2) | lw);
    const int i1 = (u0 + 1) * 32 + (((ls ^ ((u0 + 1) & 7)) << 2) | lw);
    const int i2 = (u0 + 2) * 32 + (((ls ^ ((u0 + 2) & 7)) << 2) | lw);
    const int i3 = (u0 + 3) * 32 + (((ls ^ ((u0 + 3) & 7)) << 2) | lw);

    // Pass 1: column l, rows u0..u0+3.  products A[u][l] * B[l][u]
    {
        const float4 bq = Bq[l][g ^ (l & 7)];       // B[l][u0..u0+3], LDS.128
        const float a0 = Af[i0], a1 = Af[i1], a2 = Af[i2], a3 = Af[i3];
        const float am = a0 * bq.x + a1 * bq.y + a2 * bq.z + a3 * bq.w;
        const float ar = (bq.x + bq.y) + (bq.z + bq.w);
        redA[g][l] = make_float2(am, ar);
    }
    // Pass 2: row l, cols u0..u0+3.  products A[l][v] * B[v][l]
    if (!diag) {
        const float4 aq = A4[l][g ^ (l & 7)];       // A[l][u0..u0+3], LDS.128
        const float b0 = Bf[i0], b1 = Bf[i1], b2 = Bf[i2], b3 = Bf[i3];
        const float am = aq.x * b0 + aq.y * b1 + aq.z * b2 + aq.w * b3;
        const float ar = (aq.x + aq.y) + (aq.z + aq.w);
        redB[g][l] = make_float2(am, ar);
    }
    __syncthreads();

    // Parallel final reductions: warp 0 -> pass1, warp 1 -> pass2.
    if (tid < 32) {
        float sm = 0.0f, sr = 0.0f;
        #pragma unroll
        for (int k = 0; k < 8; k++) {
            const float2 p = redA[k][tid];
            sm += p.x; sr += p.y;
        }
        g_partM[I][J * TILE + tid] = sm;
        g_partR[I][J * TILE + tid] = sr;
    } else if (tid < 64 && !diag) {
        const int u = tid & 31;
        float sm = 0.0f, sr = 0.0f;
        #pragma unroll
        for (int k = 0; k < 8; k++) {
            const float2 p = redB[k][u];
            sm += p.x; sr += p.y;
        }
        g_partM[J][I * TILE + u] = sm;
        g_partR[J][I * TILE + u] = sr;
    }
}

// ---------------------------------------------------------------------------
// Kernel 2: partials reduction, parallel over columns AND p.
// Block = 32 columns x 8 p-groups; ~1 MB of L2-hot reads across 64 blocks.
// ---------------------------------------------------------------------------
__global__ void __launch_bounds__(256) hebb_reduce_kernel(int NT, float invD)
{
    __shared__ float sM[8][33];
    __shared__ float sR[8][33];
    const int lane = threadIdx.x & 31;
    const int g    = threadIdx.x >> 5;
    const int j    = blockIdx.x * 32 + lane;

    float sm = 0.0f, sr = 0.0f;
    for (int p = g; p < NT; p += 8) {
        sm += g_partM[p][j];
        sr += g_partR[p][j];
    }
    sM[g][lane] = sm;
    sR[g][lane] = sr;
    __syncthreads();
    if (threadIdx.x < 32) {
        float m = 0.0f, r = 0.0f;
        #pragma unroll
        for (int k = 0; k < 8; k++) { m += sM[k][threadIdx.x]; r += sR[k][threadIdx.x]; }
        const int jj = blockIdx.x * 32 + threadIdx.x;
        g_m[jj]  = m * invD;
        g_rm[jj] = r * (invD * ETA);
    }
}

// ---------------------------------------------------------------------------
// Kernel 3: elementwise outputs. 1024 blocks, each handles rows 2*bid, 2*bid+1
// with ALL loads front-batched (10 LDG.128 per thread in flight).
//   y[i,j]  = kernel[i,j] * m[j]
//   nk[i,j] = kernel[i,j] + rm[i] * x[i,j]
// ---------------------------------------------------------------------------
template<int COLS4, bool NK>
__global__ void __launch_bounds__(256) hebb_ew_kernel_s(
    const float* __restrict__ x, const float* __restrict__ kmat,
    float* __restrict__ y, float* __restrict__ nk)
{
    const int tid = threadIdx.x;
    const int c0 = tid, c1 = tid + 256;
    const int row = blockIdx.x * 2;
    const size_t b0 = (size_t)row * COLS4;
    const size_t b1 = b0 + COLS4;

    const float4* m4 = reinterpret_cast<const float4*>(g_m);
    const float4* k0 = reinterpret_cast<const float4*>(kmat) + b0;
    const float4* k1 = reinterpret_cast<const float4*>(kmat) + b1;
    const float4* x0 = reinterpret_cast<const float4*>(x) + b0;
    const float4* x1 = reinterpret_cast<const float4*>(x) + b1;

    // Front-batched loads (independent -> max MLP).
    float4 ma = m4[c0], mb = m4[c1];
    float4 ka0 = k0[c0], kb0 = k0[c1];
    float4 ka1 = k1[c0], kb1 = k1[c1];
    float4 xa0, xb0, xa1, xb1;
    if (NK) { xa0 = x0[c0]; xb0 = x0[c1]; xa1 = x1[c0]; xb1 = x1[c1]; }
    const float rm0 = g_rm[row];
    const float rm1 = g_rm[row + 1];

    float4* y0 = reinterpret_cast<float4*>(y) + b0;
    float4* y1 = reinterpret_cast<float4*>(y) + b1;

    float4 v;
    v.x = ka0.x * ma.x; v.y = ka0.y * ma.y; v.z = ka0.z * ma.z; v.w = ka0.w * ma.w;
    y0[c0] = v;
    v.x = kb0.x * mb.x; v.y = kb0.y * mb.y; v.z = kb0.z * mb.z; v.w = kb0.w * mb.w;
    y0[c1] = v;
    v.x = ka1.x * ma.x; v.y = ka1.y * ma.y; v.z = ka1.z * ma.z; v.w = ka1.w * ma.w;
    y1[c0] = v;
    v.x = kb1.x * mb.x; v.y = kb1.y * mb.y; v.z = kb1.z * mb.z; v.w = kb1.w * mb.w;
    y1[c1] = v;

    if (NK) {
        float4* n0 = reinterpret_cast<float4*>(nk) + b0;
        float4* n1 = reinterpret_cast<float4*>(nk) + b1;
        v.x = fmaf(rm0, xa0.x, ka0.x); v.y = fmaf(rm0, xa0.y, ka0.y);
        v.z = fmaf(rm0, xa0.z, ka0.z); v.w = fmaf(rm0, xa0.w, ka0.w);
        n0[c0] = v;
        v.x = fmaf(rm0, xb0.x, kb0.x); v.y = fmaf(rm0, xb0.y, kb0.y);
        v.z = fmaf(rm0, xb0.z, kb0.z); v.w = fmaf(rm0, xb0.w, kb0.w);
        n0[c1] = v;
        v.x = fmaf(rm1, xa1.x, ka1.x); v.y = fmaf(rm1, xa1.y, ka1.y);
        v.z = fmaf(rm1, xa1.z, ka1.z); v.w = fmaf(rm1, xa1.w, ka1.w);
        n1[c0] = v;
        v.x = fmaf(rm1, xb1.x, kb1.x); v.y = fmaf(rm1, xb1.y, kb1.y);
        v.z = fmaf(rm1, xb1.z, kb1.z); v.w = fmaf(rm1, xb1.w, kb1.w);
        n1[c1] = v;
    }
}

// Generic fallback (runtime D4).
__global__ void __launch_bounds__(256) hebb_ew_kernel_g(
    const float* __restrict__ x, const float* __restrict__ kmat,
    float* __restrict__ y, float* __restrict__ nk, int D4, int n4, int write_nk)
{
    int idx = blockIdx.x * 256 + threadIdx.x;
    if (idx >= n4) return;
    const int col4 = idx % D4;
    const int row  = idx / D4;
    float4 kv = reinterpret_cast<const float4*>(kmat)[idx];
    float4 mv = reinterpret_cast<const float4*>(g_m)[col4];
    float4 yv;
    yv.x = kv.x * mv.x; yv.y = kv.y * mv.y; yv.z = kv.z * mv.z; yv.w = kv.w * mv.w;
    reinterpret_cast<float4*>(y)[idx] = yv;
    if (write_nk) {
        float rm = g_rm[row];
        float4 xv = reinterpret_cast<const float4*>(x)[idx];
        float4 nv;
        nv.x = fmaf(rm, xv.x, kv.x); nv.y = fmaf(rm, xv.y, kv.y);
        nv.z = fmaf(rm, xv.z, kv.z); nv.w = fmaf(rm, xv.w, kv.w);
        reinterpret_cast<float4*>(nk)[idx] = nv;
    }
}

extern "C" void kernel_launch(void* const* d_in, const int* in_sizes, int n_in,
                              void* d_out, int out_size)
{
    if (n_in < 2 || !d_in || !d_out || !in_sizes) return;

    const float* x    = (const float*)d_in[0];
    const float* kmat = (const float*)d_in[1];
    float* out        = (float*)d_out;

    const int n = in_sizes[0];           // D*D
    int D = 1;
    while (D < MAXD && D * D < n) D++;   // D = 2048 here
    if (D * D != n || (D % TILE) != 0) return;

    const int NT = D / TILE;              // 64
    const int nPairs = NT * (NT + 1) / 2; // 2080
    const int write_nk = (out_size >= 2 * n) ? 1 : 0;
    const float invD = 1.0f / (float)D;

    float* y  = out;
    float* nk = out + n;

    hebb_tile_kernel<<<nPairs, 256>>>(x, D, NT);
    hebb_reduce_kernel<<<D / 32, 256>>>(NT, invD);

    if (D == 2048) {
        if (write_nk)
            hebb_ew_kernel_s<512, true><<<1024, 256>>>(x, kmat, y, nk);
        else
            hebb_ew_kernel_s<512, false><<<1024, 256>>>(x, kmat, y, nk);
    } else {
        const int n4 = n >> 2;
        hebb_ew_kernel_g<<<(n4 + 255) / 256, 256>>>(x, kmat, y, nk, D >> 2, n4, write_nk);
    }
}

// round 11
// speedup vs baseline: 1.0104x; 1.0104x over previous
#include <cuda_runtime.h>
#include <math.h>

#define MAXD 2048
#define TILE 32
#define NTMAX (MAXD / TILE)     // 64
#define ETA 0.005f

// Disjoint partials: slot [p][j] = contribution of tile p to column/row j.
// Every slot written exactly once per launch -> no zeroing, no atomics, no fences.
__device__ float g_partM[NTMAX][MAXD];   // 512 KB
__device__ float g_partR[NTMAX][MAXD];   // 512 KB
__device__ float g_m[MAXD];              // m[j]           (pre-scaled by 1/D)
__device__ float g_rm[MAXD];             // rowmean[b] * ETA / D

// ---------------------------------------------------------------------------
// Kernel 1: symmetric tile-pair reduction, overhead-optimized.
//  * 2D grid (NT, NT): I = by, J = bx; lower-triangle blocks exit in 2 instrs
//    (replaces the sqrt/while triangular inversion executed by every thread).
//  * Padded float4[32][9] tiles (word stride 36): no XOR swizzle math.
//      - fill:      1 LDG.128 + 1 STS.128 (lanes 0..7 -> words 4c4: banks 0..31)
//      - row read:  LDS.128 at word l*36+g*4 (conflict-free per 8-lane phase)
//      - col read:  scalar at base + {0,36,72,108} (addr = const + l: c-free)
//  * Both passes back-to-back (A/B read-only), ONE sync, warps 0/1 reduce.
// Block {I,J}, I<=J: A = x[I,J], B = x[J,I].
//   pass 1: partM[I][J*32+l] = sum_u A[u][l]*B[l][u]; partR[I][J*32+l] = sum_u B[l][u]
//   pass 2: partM[J][I*32+l] = sum_v A[l][v]*B[v][l]; partR[J][I*32+l] = sum_v A[l][v]
// Diagonal (I==J): pass 1 only with B := A.
// ---------------------------------------------------------------------------
__global__ void __launch_bounds__(256) hebb_tile_kernel(
    const float* __restrict__ x, int D)
{
    const int I = blockIdx.y;
    const int J = blockIdx.x;
    if (J < I) return;                 // lower triangle: no-op block

    __shared__ float4 A4[32][9];       // padded: word stride 36 per row
    __shared__ float4 B4[32][9];
    __shared__ float2 redA[8][32];
    __shared__ float2 redB[8][32];

    const int tid = threadIdx.x;
    const int r   = tid >> 3;          // 0..31 (row within tile)
    const int c4  = tid & 7;           // float4 column
    const bool diag = (I == J);

    // Fill tiles: one LDG.128 -> one STS.128 (no swizzle).
    A4[r][c4] = *reinterpret_cast<const float4*>(
        x + (size_t)(I * TILE + r) * D + J * TILE + (c4 << 2));
    if (!diag)
        B4[r][c4] = *reinterpret_cast<const float4*>(
            x + (size_t)(J * TILE + r) * D + I * TILE + (c4 << 2));
    __syncthreads();

    const float* Af = reinterpret_cast<const float*>(A4);
    const float* Bf = diag ? Af : reinterpret_cast<const float*>(B4);
    const float4 (*Bq)[9] = diag ? A4 : B4;

    const int g  = tid >> 5;           // 0..7  (warp id = 4-row group)
    const int l  = tid & 31;           // lane  (col in pass1 / row in pass2)
    const int base = (g << 2) * 36 + l; // word index of (u0, l); offsets +0,36,72,108

    // Pass 1: column l, rows u0..u0+3.  products A[u][l] * B[l][u]
    {
        const float4 bq = Bq[l][g];                       // B[l][u0..u0+3]
        const float am = Af[base]       * bq.x + Af[base + 36]  * bq.y
                       + Af[base + 72]  * bq.z + Af[base + 108] * bq.w;
        const float ar = (bq.x + bq.y) + (bq.z + bq.w);
        redA[g][l] = make_float2(am, ar);
    }
    // Pass 2: row l, cols u0..u0+3.  products A[l][v] * B[v][l]
    if (!diag) {
        const float4 aq = A4[l][g];                       // A[l][u0..u0+3]
        const float am = aq.x * Bf[base]      + aq.y * Bf[base + 36]
                       + aq.z * Bf[base + 72] + aq.w * Bf[base + 108];
        const float ar = (aq.x + aq.y) + (aq.z + aq.w);
        redB[g][l] = make_float2(am, ar);
    }
    __syncthreads();

    // Parallel final reductions: warp 0 -> pass1, warp 1 -> pass2.
    if (tid < 32) {
        float sm = 0.0f, sr = 0.0f;
        #pragma unroll
        for (int k = 0; k < 8; k++) {
            const float2 p = redA[k][tid];
            sm += p.x; sr += p.y;
        }
        g_partM[I][J * TILE + tid] = sm;
        g_partR[I][J * TILE + tid] = sr;
    } else if (tid < 64 && !diag) {
        const int u = tid & 31;
        float sm = 0.0f, sr = 0.0f;
        #pragma unroll
        for (int k = 0; k < 8; k++) {
            const float2 p = redB[k][u];
            sm += p.x; sr += p.y;
        }
        g_partM[J][I * TILE + u] = sm;
        g_partR[J][I * TILE + u] = sr;
    }
}

// ---------------------------------------------------------------------------
// Kernel 2: partials reduction, parallel over columns AND p.
// Block = 32 columns x 8 p-groups; ~1 MB of L2-hot reads across 64 blocks.
// ---------------------------------------------------------------------------
__global__ void __launch_bounds__(256) hebb_reduce_kernel(int NT, float invD)
{
    __shared__ float sM[8][33];
    __shared__ float sR[8][33];
    const int lane = threadIdx.x & 31;
    const int g    = threadIdx.x >> 5;
    const int j    = blockIdx.x * 32 + lane;

    float sm = 0.0f, sr = 0.0f;
    for (int p = g; p < NT; p += 8) {
        sm += g_partM[p][j];
        sr += g_partR[p][j];
    }
    sM[g][lane] = sm;
    sR[g][lane] = sr;
    __syncthreads();
    if (threadIdx.x < 32) {
        float m = 0.0f, r = 0.0f;
        #pragma unroll
        for (int k = 0; k < 8; k++) { m += sM[k][threadIdx.x]; r += sR[k][threadIdx.x]; }
        const int jj = blockIdx.x * 32 + threadIdx.x;
        g_m[jj]  = m * invD;
        g_rm[jj] = r * (invD * ETA);
    }
}

// ---------------------------------------------------------------------------
// Kernel 3: elementwise outputs. 1024 blocks, each handles rows 2*bid, 2*bid+1
// with ALL loads front-batched (10 LDG.128 per thread in flight).
//   y[i,j]  = kernel[i,j] * m[j]
//   nk[i,j] = kernel[i,j] + rm[i] * x[i,j]
// ---------------------------------------------------------------------------
template<int COLS4, bool NK>
__global__ void __launch_bounds__(256) hebb_ew_kernel_s(
    const float* __restrict__ x, const float* __restrict__ kmat,
    float* __restrict__ y, float* __restrict__ nk)
{
    const int tid = threadIdx.x;
    const int c0 = tid, c1 = tid + 256;
    const int row = blockIdx.x * 2;
    const size_t b0 = (size_t)row * COLS4;
    const size_t b1 = b0 + COLS4;

    const float4* m4 = reinterpret_cast<const float4*>(g_m);
    const float4* k0 = reinterpret_cast<const float4*>(kmat) + b0;
    const float4* k1 = reinterpret_cast<const float4*>(kmat) + b1;
    const float4* x0 = reinterpret_cast<const float4*>(x) + b0;
    const float4* x1 = reinterpret_cast<const float4*>(x) + b1;

    // Front-batched loads (independent -> max MLP).
    float4 ma = m4[c0], mb = m4[c1];
    float4 ka0 = k0[c0], kb0 = k0[c1];
    float4 ka1 = k1[c0], kb1 = k1[c1];
    float4 xa0, xb0, xa1, xb1;
    if (NK) { xa0 = x0[c0]; xb0 = x0[c1]; xa1 = x1[c0]; xb1 = x1[c1]; }
    const float rm0 = g_rm[row];
    const float rm1 = g_rm[row + 1];

    float4* y0 = reinterpret_cast<float4*>(y) + b0;
    float4* y1 = reinterpret_cast<float4*>(y) + b1;

    float4 v;
    v.x = ka0.x * ma.x; v.y = ka0.y * ma.y; v.z = ka0.z * ma.z; v.w = ka0.w * ma.w;
    y0[c0] = v;
    v.x = kb0.x * mb.x; v.y = kb0.y * mb.y; v.z = kb0.z * mb.z; v.w = kb0.w * mb.w;
    y0[c1] = v;
    v.x = ka1.x * ma.x; v.y = ka1.y * ma.y; v.z = ka1.z * ma.z; v.w = ka1.w * ma.w;
    y1[c0] = v;
    v.x = kb1.x * mb.x; v.y = kb1.y * mb.y; v.z = kb1.z * mb.z; v.w = kb1.w * mb.w;
    y1[c1] = v;

    if (NK) {
        float4* n0 = reinterpret_cast<float4*>(nk) + b0;
        float4* n1 = reinterpret_cast<float4*>(nk) + b1;
        v.x = fmaf(rm0, xa0.x, ka0.x); v.y = fmaf(rm0, xa0.y, ka0.y);
        v.z = fmaf(rm0, xa0.z, ka0.z); v.w = fmaf(rm0, xa0.w, ka0.w);
        n0[c0] = v;
        v.x = fmaf(rm0, xb0.x, kb0.x); v.y = fmaf(rm0, xb0.y, kb0.y);
        v.z = fmaf(rm0, xb0.z, kb0.z); v.w = fmaf(rm0, xb0.w, kb0.w);
        n0[c1] = v;
        v.x = fmaf(rm1, xa1.x, ka1.x); v.y = fmaf(rm1, xa1.y, ka1.y);
        v.z = fmaf(rm1, xa1.z, ka1.z); v.w = fmaf(rm1, xa1.w, ka1.w);
        n1[c0] = v;
        v.x = fmaf(rm1, xb1.x, kb1.x); v.y = fmaf(rm1, xb1.y, kb1.y);
        v.z = fmaf(rm1, xb1.z, kb1.z); v.w = fmaf(rm1, xb1.w, kb1.w);
        n1[c1] = v;
    }
}

// Generic fallback (runtime D4).
__global__ void __launch_bounds__(256) hebb_ew_kernel_g(
    const float* __restrict__ x, const float* __restrict__ kmat,
    float* __restrict__ y, float* __restrict__ nk, int D4, int n4, int write_nk)
{
    int idx = blockIdx.x * 256 + threadIdx.x;
    if (idx >= n4) return;
    const int col4 = idx % D4;
    const int row  = idx / D4;
    float4 kv = reinterpret_cast<const float4*>(kmat)[idx];
    float4 mv = reinterpret_cast<const float4*>(g_m)[col4];
    float4 yv;
    yv.x = kv.x * mv.x; yv.y = kv.y * mv.y; yv.z = kv.z * mv.z; yv.w = kv.w * mv.w;
    reinterpret_cast<float4*>(y)[idx] = yv;
    if (write_nk) {
        float rm = g_rm[row];
        float4 xv = reinterpret_cast<const float4*>(x)[idx];
        float4 nv;
        nv.x = fmaf(rm, xv.x, kv.x); nv.y = fmaf(rm, xv.y, kv.y);
        nv.z = fmaf(rm, xv.z, kv.z); nv.w = fmaf(rm, xv.w, kv.w);
        reinterpret_cast<float4*>(nk)[idx] = nv;
    }
}

extern "C" void kernel_launch(void* const* d_in, const int* in_sizes, int n_in,
                              void* d_out, int out_size)
{
    if (n_in < 2 || !d_in || !d_out || !in_sizes) return;

    const float* x    = (const float*)d_in[0];
    const float* kmat = (const float*)d_in[1];
    float* out        = (float*)d_out;

    const int n = in_sizes[0];           // D*D
    int D = 1;
    while (D < MAXD && D * D < n) D++;   // D = 2048 here
    if (D * D != n || (D % TILE) != 0) return;

    const int NT = D / TILE;              // 64
    const int write_nk = (out_size >= 2 * n) ? 1 : 0;
    const float invD = 1.0f / (float)D;

    float* y  = out;
    float* nk = out + n;

    dim3 tgrid(NT, NT);
    hebb_tile_kernel<<<tgrid, 256>>>(x, D);
    hebb_reduce_kernel<<<D / 32, 256>>>(NT, invD);

    if (D == 2048) {
        if (write_nk)
            hebb_ew_kernel_s<512, true><<<1024, 256>>>(x, kmat, y, nk);
        else
            hebb_ew_kernel_s<512, false><<<1024, 256>>>(x, kmat, y, nk);
    } else {
        const int n4 = n >> 2;
        hebb_ew_kernel_g<<<(n4 + 255) / 256, 256>>>(x, kmat, y, nk, D >> 2, n4, write_nk);
    }
}